// round 6
// baseline (speedup 1.0000x reference)
#include <cuda_runtime.h>
#include <cuda_bf16.h>
#include <math_constants.h>

#define M_PTS 8192
#define C_DIM 64
#define KNN 20
#define NSPLIT 2
#define SPAN (M_PTS / NSPLIT)   // candidates per split
#define QB 128                  // queries (=threads) per knn block
#define CT 64                   // candidate tile

typedef unsigned long long ull;

// ---------------- scratch (device globals; no allocation allowed) -------------
__device__ float g_sq[M_PTS];
__device__ float g_pd[NSPLIT * M_PTS * KNN];
__device__ int   g_pi[NSPLIT * M_PTS * KNN];
__device__ int   g_knn[M_PTS * KNN];
__device__ float g_gb[M_PTS * C_DIM];   // Wb^T f
__device__ float g_u [M_PTS * C_DIM];   // b1 + Wa^T f - Wb^T f

// ---------------- f32x2 helpers ----------------------------------------------
__device__ __forceinline__ ull ffma2(ull a, ull b, ull c) {
    ull d;
    asm("fma.rn.f32x2 %0, %1, %2, %3;" : "=l"(d) : "l"(a), "l"(b), "l"(c));
    return d;
}
__device__ __forceinline__ ull addf2(ull a, ull b) {
    ull d;
    asm("add.rn.f32x2 %0, %1, %2;" : "=l"(d) : "l"(a), "l"(b));
    return d;
}
__device__ __forceinline__ ull pack2(float x, float y) {
    ull r;
    asm("mov.b64 %0, {%1, %2};" : "=l"(r) : "f"(x), "f"(y));
    return r;
}
__device__ __forceinline__ void unpack2(ull v, float& lo, float& hi) {
    asm("mov.b64 {%0, %1}, %2;" : "=f"(lo), "=f"(hi) : "l"(v));
}

// ---------------- kernel 0: squared norms ------------------------------------
__global__ void sq_kernel(const float* __restrict__ pos) {
    int i = blockIdx.x * blockDim.x + threadIdx.x;
    if (i >= M_PTS) return;
    const float4* p4 = reinterpret_cast<const float4*>(pos + i * C_DIM);
    float s = 0.f;
#pragma unroll
    for (int v = 0; v < C_DIM / 4; v++) {
        float4 a = p4[v];
        s += a.x * a.x + a.y * a.y + a.z * a.z + a.w * a.w;
    }
    g_sq[i] = s;
}

// ---------------- kernel 1: partial KNN --------------------------------------
// Per-thread top-K lists live in SMEM, plane-major [KNN][QB]: address stride of
// 128 floats => bank == tid%32 for ANY list slot => conflict-free divergent
// access; no local-memory demotion.
__global__ __launch_bounds__(QB) void knn_part(const float* __restrict__ pos) {
    const int tid = threadIdx.x;
    const int q = blockIdx.x * QB + tid;
    const int split = blockIdx.y;
    const int cand0 = split * SPAN;
    const int cand1 = cand0 + SPAN;

    const float4* pos4 = reinterpret_cast<const float4*>(pos);

    __shared__ float4 tile[CT * (C_DIM / 4)];   // 16 KB
    __shared__ float tsq[CT];
    __shared__ float bdl[KNN * QB];             // 10 KB
    __shared__ int   bil[KNN * QB];             // 10 KB

    // query packed as 32 x f32x2
    ull q2[C_DIM / 2];
#pragma unroll
    for (int v = 0; v < C_DIM / 4; v++) {
        float4 a = pos4[q * (C_DIM / 4) + v];
        q2[2 * v]     = pack2(a.x, a.y);
        q2[2 * v + 1] = pack2(a.z, a.w);
    }
    const float myq = g_sq[q];

#pragma unroll
    for (int i = 0; i < KNN; i++) {
        bdl[i * QB + tid] = CUDART_INF_F;
        bil[i * QB + tid] = -1;
    }
    float cmax = CUDART_INF_F;
    int cpos = 0;

    for (int t0 = cand0; t0 < cand1; t0 += CT) {
        __syncthreads();
#pragma unroll
        for (int i = 0; i < (CT * (C_DIM / 4)) / QB; i++) {
            int fl = i * QB + tid;
            tile[fl] = pos4[t0 * (C_DIM / 4) + fl];
        }
        if (tid < CT) tsq[tid] = g_sq[t0 + tid];
        __syncthreads();

        // 16 ulonglong2 (= 64 floats) per candidate row
        const ulonglong2* tl = reinterpret_cast<const ulonglong2*>(tile);
        for (int j = 0; j < CT; j += 4) {
            ull a00 = 0, a01 = 0, a10 = 0, a11 = 0;
            ull a20 = 0, a21 = 0, a30 = 0, a31 = 0;
#pragma unroll
            for (int v = 0; v < 16; v++) {
                ulonglong2 c0 = tl[(j + 0) * 16 + v];
                ulonglong2 c1 = tl[(j + 1) * 16 + v];
                ulonglong2 c2 = tl[(j + 2) * 16 + v];
                ulonglong2 c3 = tl[(j + 3) * 16 + v];
                ull qa = q2[2 * v], qb = q2[2 * v + 1];
                a00 = ffma2(qa, c0.x, a00);  a01 = ffma2(qb, c0.y, a01);
                a10 = ffma2(qa, c1.x, a10);  a11 = ffma2(qb, c1.y, a11);
                a20 = ffma2(qa, c2.x, a20);  a21 = ffma2(qb, c2.y, a21);
                a30 = ffma2(qa, c3.x, a30);  a31 = ffma2(qb, c3.y, a31);
            }
            float dsc[4];
            {
                float lo, hi;
                ull s0 = addf2(a00, a01); unpack2(s0, lo, hi);
                dsc[0] = fmaf(-2.0f, lo + hi, myq + tsq[j + 0]);
                ull s1 = addf2(a10, a11); unpack2(s1, lo, hi);
                dsc[1] = fmaf(-2.0f, lo + hi, myq + tsq[j + 1]);
                ull s2 = addf2(a20, a21); unpack2(s2, lo, hi);
                dsc[2] = fmaf(-2.0f, lo + hi, myq + tsq[j + 2]);
                ull s3 = addf2(a30, a31); unpack2(s3, lo, hi);
                dsc[3] = fmaf(-2.0f, lo + hi, myq + tsq[j + 3]);
            }
#pragma unroll
            for (int u = 0; u < 4; u++) {
                if (dsc[u] < cmax) {
                    bdl[cpos * QB + tid] = dsc[u];
                    bil[cpos * QB + tid] = t0 + j + u;
                    // tournament argmax over the 20-entry smem list (regs only)
                    float mv[KNN]; int mi[KNN];
#pragma unroll
                    for (int i = 0; i < KNN; i++) {
                        mv[i] = bdl[i * QB + tid];
                        mi[i] = i;
                    }
#pragma unroll
                    for (int s = 1; s < KNN; s *= 2) {
#pragma unroll
                        for (int i = 0; i + s < KNN; i += 2 * s) {
                            if (mv[i + s] > mv[i]) { mv[i] = mv[i + s]; mi[i] = mi[i + s]; }
                        }
                    }
                    cmax = mv[0]; cpos = mi[0];
                }
            }
        }
    }

    const int base = (split * M_PTS + q) * KNN;
#pragma unroll
    for (int i = 0; i < KNN; i++) {
        g_pd[base + i] = bdl[i * QB + tid];
        g_pi[base + i] = bil[i * QB + tid];
    }
}

// ---------------- kernel 2: merge the partial lists ---------------------------
__global__ __launch_bounds__(128) void knn_merge() {
    int q = blockIdx.x * blockDim.x + threadIdx.x;
    if (q >= M_PTS) return;
    float d[NSPLIT * KNN];
    int id[NSPLIT * KNN];
#pragma unroll
    for (int h = 0; h < NSPLIT; h++)
#pragma unroll
        for (int i = 0; i < KNN; i++) {
            d[h * KNN + i] = g_pd[(h * M_PTS + q) * KNN + i];
            id[h * KNN + i] = g_pi[(h * M_PTS + q) * KNN + i];
        }
    for (int s = 0; s < KNN; s++) {
        float bm = d[0]; int bp = 0;
        for (int i = 1; i < NSPLIT * KNN; i++) {
            if (d[i] < bm || (d[i] == bm && id[i] < id[bp])) { bm = d[i]; bp = i; }
        }
        g_knn[q * KNN + s] = id[bp];
        d[bp] = CUDART_INF_F;
    }
}

// ---------------- kernel 3: precompute u[p], g[p] -----------------------------
// h_k(q) = relu(u[q] + g[nbr_k]),  g[p] = Wb^T f_p,  u[q] = b1 + Wa^T f_q - g[q]
__global__ __launch_bounds__(256) void pre_kernel(
    const float* __restrict__ f,
    const float* __restrict__ W1, const float* __restrict__ b1)
{
    __shared__ float W1s[128 * 64];
    __shared__ float fs[32 * 64];
    const int tid = threadIdx.x;
    for (int i = tid; i < 128 * 64; i += 256) W1s[i] = W1[i];
    const int p0 = blockIdx.x * 32;
    for (int i = tid; i < 32 * 64; i += 256) fs[i] = f[p0 * 64 + i];
    __syncthreads();

    const int o = tid & 63;
    const int sub = tid >> 6;
    const float bb1 = b1[o];
    for (int pi = sub; pi < 32; pi += 4) {
        float u = bb1, g = 0.f;
#pragma unroll
        for (int c = 0; c < 64; c++) {
            float fv = fs[pi * 64 + c];
            u = fmaf(fv, W1s[c * 64 + o], u);
            g = fmaf(fv, W1s[(64 + c) * 64 + o], g);
        }
        g_gb[(p0 + pi) * 64 + o] = g;
        g_u [(p0 + pi) * 64 + o] = u - g;
    }
}

// ---------------- kernel 4: layer2 + max aggregation --------------------------
__global__ __launch_bounds__(128) void mlp_kernel(
    const float* __restrict__ W2, const float* __restrict__ b2,
    float* __restrict__ out)
{
    __shared__ float W2s[64 * 64];
    __shared__ float hs[2][KNN * 64];
    __shared__ int sidx[2][KNN];

    const int tid = threadIdx.x;
    const int sub = tid >> 6;
    const int o = tid & 63;
    const int q = blockIdx.x * 2 + sub;

    for (int i = tid; i < 64 * 64; i += 128) W2s[i] = W2[i];
    if (o < KNN) sidx[sub][o] = g_knn[q * KNN + o];
    __syncthreads();

    const float u = g_u[q * 64 + o];
#pragma unroll
    for (int k = 0; k < KNN; k++) {
        int nb = sidx[sub][k];
        hs[sub][k * 64 + o] = fmaxf(u + g_gb[nb * 64 + o], 0.f);
    }
    __syncthreads();

    float acc[KNN];
#pragma unroll
    for (int k = 0; k < KNN; k++) acc[k] = 0.f;
#pragma unroll
    for (int c = 0; c < 64; c++) {
        float w = W2s[c * 64 + o];
#pragma unroll
        for (int k = 0; k < KNN; k++)
            acc[k] = fmaf(hs[sub][k * 64 + c], w, acc[k]);
    }
    float v = acc[0];
#pragma unroll
    for (int k = 1; k < KNN; k++) v = fmaxf(v, acc[k]);
    out[q * 64 + o] = v + b2[o];
}

// ---------------- launch -------------------------------------------------------
extern "C" void kernel_launch(void* const* d_in, const int* in_sizes, int n_in,
                              void* d_out, int out_size)
{
    const float* pos  = (const float*)d_in[0];
    const float* feat = (const float*)d_in[1];
    const float* W1   = (const float*)d_in[2];
    const float* b1   = (const float*)d_in[3];
    const float* W2   = (const float*)d_in[4];
    const float* b2   = (const float*)d_in[5];
    float* out = (float*)d_out;

    sq_kernel<<<(M_PTS + 255) / 256, 256>>>(pos);

    dim3 kg(M_PTS / QB, NSPLIT);
    knn_part<<<kg, QB>>>(pos);

    knn_merge<<<(M_PTS + 127) / 128, 128>>>();

    pre_kernel<<<M_PTS / 32, 256>>>(feat, W1, b1);

    mlp_kernel<<<M_PTS / 2, 128>>>(W2, b2, out);
}

// round 7
// speedup vs baseline: 2.0007x; 2.0007x over previous
#include <cuda_runtime.h>
#include <cuda_bf16.h>
#include <math_constants.h>

#define M_PTS 8192
#define C_DIM 64
#define KNN 20
#define NSPLIT 4
#define SPAN (M_PTS / NSPLIT)   // candidates per split
#define QB 128                  // queries (=threads) per knn block
#define CT 128                  // candidate tile

typedef unsigned long long ull;

// ---------------- scratch (device globals; no allocation allowed) -------------
__device__ float g_sq[M_PTS];
__device__ float g_pd[NSPLIT * M_PTS * KNN];
__device__ int   g_pi[NSPLIT * M_PTS * KNN];
__device__ int   g_knn[M_PTS * KNN];
__device__ float g_gb[M_PTS * C_DIM];   // Wb^T f
__device__ float g_u [M_PTS * C_DIM];   // b1 + Wa^T f - Wb^T f

// ---------------- f32x2 helpers ----------------------------------------------
__device__ __forceinline__ ull ffma2(ull a, ull b, ull c) {
    ull d;
    asm("fma.rn.f32x2 %0, %1, %2, %3;" : "=l"(d) : "l"(a), "l"(b), "l"(c));
    return d;
}
__device__ __forceinline__ ull addf2(ull a, ull b) {
    ull d;
    asm("add.rn.f32x2 %0, %1, %2;" : "=l"(d) : "l"(a), "l"(b));
    return d;
}
__device__ __forceinline__ ull pack2(float x, float y) {
    ull r;
    asm("mov.b64 %0, {%1, %2};" : "=l"(r) : "f"(x), "f"(y));
    return r;
}
__device__ __forceinline__ void unpack2(ull v, float& lo, float& hi) {
    asm("mov.b64 {%0, %1}, %2;" : "=f"(lo), "=f"(hi) : "l"(v));
}

// ---------------- kernel 0: squared norms ------------------------------------
__global__ void sq_kernel(const float* __restrict__ pos) {
    int i = blockIdx.x * blockDim.x + threadIdx.x;
    if (i >= M_PTS) return;
    const float4* p4 = reinterpret_cast<const float4*>(pos + i * C_DIM);
    float s = 0.f;
#pragma unroll
    for (int v = 0; v < C_DIM / 4; v++) {
        float4 a = p4[v];
        s += a.x * a.x + a.y * a.y + a.z * a.z + a.w * a.w;
    }
    g_sq[i] = s;
}

// ---------------- kernel 1: partial KNN --------------------------------------
// Sorted top-K in REGISTERS; insertion = fully static predicated swap chain.
__global__ __launch_bounds__(QB) void knn_part(const float* __restrict__ pos) {
    const int tid = threadIdx.x;
    const int q = blockIdx.x * QB + tid;
    const int split = blockIdx.y;
    const int cand0 = split * SPAN;
    const int cand1 = cand0 + SPAN;

    const float4* pos4 = reinterpret_cast<const float4*>(pos);

    // query packed as 32 x f32x2
    ull q2[C_DIM / 2];
#pragma unroll
    for (int v = 0; v < C_DIM / 4; v++) {
        float4 a = pos4[q * (C_DIM / 4) + v];
        q2[2 * v]     = pack2(a.x, a.y);
        q2[2 * v + 1] = pack2(a.z, a.w);
    }
    const float myq = g_sq[q];

    // sorted ascending; bd[KNN-1] is the current worst kept
    float bd[KNN];
    int bi[KNN];
#pragma unroll
    for (int i = 0; i < KNN; i++) { bd[i] = CUDART_INF_F; bi[i] = -1; }

    __shared__ float4 tile[CT * (C_DIM / 4)];
    __shared__ float tsq[CT];

    for (int t0 = cand0; t0 < cand1; t0 += CT) {
        __syncthreads();
#pragma unroll
        for (int i = 0; i < (CT * (C_DIM / 4)) / QB; i++) {
            int fl = i * QB + tid;
            tile[fl] = pos4[t0 * (C_DIM / 4) + fl];
        }
        tsq[tid] = g_sq[t0 + tid];   // QB == CT
        __syncthreads();

        // 16 ulonglong2 (= 64 floats) per candidate row
        const ulonglong2* tl = reinterpret_cast<const ulonglong2*>(tile);
        for (int j = 0; j < CT; j += 4) {
            ull a00 = 0, a01 = 0, a10 = 0, a11 = 0;
            ull a20 = 0, a21 = 0, a30 = 0, a31 = 0;
#pragma unroll
            for (int v = 0; v < 16; v++) {
                ulonglong2 c0 = tl[(j + 0) * 16 + v];
                ulonglong2 c1 = tl[(j + 1) * 16 + v];
                ulonglong2 c2 = tl[(j + 2) * 16 + v];
                ulonglong2 c3 = tl[(j + 3) * 16 + v];
                ull qa = q2[2 * v], qb = q2[2 * v + 1];
                a00 = ffma2(qa, c0.x, a00);  a01 = ffma2(qb, c0.y, a01);
                a10 = ffma2(qa, c1.x, a10);  a11 = ffma2(qb, c1.y, a11);
                a20 = ffma2(qa, c2.x, a20);  a21 = ffma2(qb, c2.y, a21);
                a30 = ffma2(qa, c3.x, a30);  a31 = ffma2(qb, c3.y, a31);
            }
            float dsc[4];
            {
                float lo, hi;
                ull s0 = addf2(a00, a01); unpack2(s0, lo, hi);
                dsc[0] = fmaf(-2.0f, lo + hi, myq + tsq[j + 0]);
                ull s1 = addf2(a10, a11); unpack2(s1, lo, hi);
                dsc[1] = fmaf(-2.0f, lo + hi, myq + tsq[j + 1]);
                ull s2 = addf2(a20, a21); unpack2(s2, lo, hi);
                dsc[2] = fmaf(-2.0f, lo + hi, myq + tsq[j + 2]);
                ull s3 = addf2(a30, a31); unpack2(s3, lo, hi);
                dsc[3] = fmaf(-2.0f, lo + hi, myq + tsq[j + 3]);
            }
#pragma unroll
            for (int u = 0; u < 4; u++) {
                if (dsc[u] < bd[KNN - 1]) {
                    float cd = dsc[u];
                    int ci = t0 + j + u;
                    // static predicated swap chain keeps list sorted ascending;
                    // strict < preserves lowest-index-on-tie (scan order is
                    // ascending candidate index)
#pragma unroll
                    for (int i = 0; i < KNN; i++) {
                        bool sw = cd < bd[i];
                        float tf = bd[i]; int ti = bi[i];
                        bd[i] = sw ? cd : bd[i];
                        bi[i] = sw ? ci : bi[i];
                        cd = sw ? tf : cd;
                        ci = sw ? ti : ci;
                    }
                }
            }
        }
    }

    const int base = (split * M_PTS + q) * KNN;
#pragma unroll
    for (int i = 0; i < KNN; i++) { g_pd[base + i] = bd[i]; g_pi[base + i] = bi[i]; }
}

// ---------------- kernel 2: merge the partial lists ---------------------------
__global__ __launch_bounds__(128) void knn_merge() {
    int q = blockIdx.x * blockDim.x + threadIdx.x;
    if (q >= M_PTS) return;
    float d[NSPLIT * KNN];
    int id[NSPLIT * KNN];
#pragma unroll
    for (int h = 0; h < NSPLIT; h++)
#pragma unroll
        for (int i = 0; i < KNN; i++) {
            d[h * KNN + i] = g_pd[(h * M_PTS + q) * KNN + i];
            id[h * KNN + i] = g_pi[(h * M_PTS + q) * KNN + i];
        }
    // each partial list is sorted; 4-way merge by head compare
    int hp[NSPLIT];
#pragma unroll
    for (int h = 0; h < NSPLIT; h++) hp[h] = 0;
    for (int s = 0; s < KNN; s++) {
        float bm = CUDART_INF_F; int bh = 0; int bid_ = 0x7fffffff;
#pragma unroll
        for (int h = 0; h < NSPLIT; h++) {
            float dv = d[h * KNN + hp[h]];
            int iv = id[h * KNN + hp[h]];
            if (dv < bm || (dv == bm && iv < bid_)) { bm = dv; bh = h; bid_ = iv; }
        }
        g_knn[q * KNN + s] = bid_;
        hp[bh]++;
    }
}

// ---------------- kernel 3: precompute u[p], g[p] -----------------------------
// h_k(q) = relu(u[q] + g[nbr_k]),  g[p] = Wb^T f_p,  u[q] = b1 + Wa^T f_q - g[q]
__global__ __launch_bounds__(256) void pre_kernel(
    const float* __restrict__ f,
    const float* __restrict__ W1, const float* __restrict__ b1)
{
    __shared__ float W1s[128 * 64];
    __shared__ float fs[32 * 64];
    const int tid = threadIdx.x;
    for (int i = tid; i < 128 * 64; i += 256) W1s[i] = W1[i];
    const int p0 = blockIdx.x * 32;
    for (int i = tid; i < 32 * 64; i += 256) fs[i] = f[p0 * 64 + i];
    __syncthreads();

    const int o = tid & 63;
    const int sub = tid >> 6;
    const float bb1 = b1[o];
    for (int pi = sub; pi < 32; pi += 4) {
        float u = bb1, g = 0.f;
#pragma unroll
        for (int c = 0; c < 64; c++) {
            float fv = fs[pi * 64 + c];
            u = fmaf(fv, W1s[c * 64 + o], u);
            g = fmaf(fv, W1s[(64 + c) * 64 + o], g);
        }
        g_gb[(p0 + pi) * 64 + o] = g;
        g_u [(p0 + pi) * 64 + o] = u - g;
    }
}

// ---------------- kernel 4: layer2 + max aggregation --------------------------
__global__ __launch_bounds__(128) void mlp_kernel(
    const float* __restrict__ W2, const float* __restrict__ b2,
    float* __restrict__ out)
{
    __shared__ float W2s[64 * 64];
    __shared__ float hs[2][KNN * 64];
    __shared__ int sidx[2][KNN];

    const int tid = threadIdx.x;
    const int sub = tid >> 6;
    const int o = tid & 63;
    const int q = blockIdx.x * 2 + sub;

    for (int i = tid; i < 64 * 64; i += 128) W2s[i] = W2[i];
    if (o < KNN) sidx[sub][o] = g_knn[q * KNN + o];
    __syncthreads();

    const float u = g_u[q * 64 + o];
#pragma unroll
    for (int k = 0; k < KNN; k++) {
        int nb = sidx[sub][k];
        hs[sub][k * 64 + o] = fmaxf(u + g_gb[nb * 64 + o], 0.f);
    }
    __syncthreads();

    float acc[KNN];
#pragma unroll
    for (int k = 0; k < KNN; k++) acc[k] = 0.f;
#pragma unroll
    for (int c = 0; c < 64; c++) {
        float w = W2s[c * 64 + o];
#pragma unroll
        for (int k = 0; k < KNN; k++)
            acc[k] = fmaf(hs[sub][k * 64 + c], w, acc[k]);
    }
    float v = acc[0];
#pragma unroll
    for (int k = 1; k < KNN; k++) v = fmaxf(v, acc[k]);
    out[q * 64 + o] = v + b2[o];
}

// ---------------- launch -------------------------------------------------------
extern "C" void kernel_launch(void* const* d_in, const int* in_sizes, int n_in,
                              void* d_out, int out_size)
{
    const float* pos  = (const float*)d_in[0];
    const float* feat = (const float*)d_in[1];
    const float* W1   = (const float*)d_in[2];
    const float* b1   = (const float*)d_in[3];
    const float* W2   = (const float*)d_in[4];
    const float* b2   = (const float*)d_in[5];
    float* out = (float*)d_out;

    sq_kernel<<<(M_PTS + 255) / 256, 256>>>(pos);

    dim3 kg(M_PTS / QB, NSPLIT);
    knn_part<<<kg, QB>>>(pos);

    knn_merge<<<(M_PTS + 127) / 128, 128>>>();

    pre_kernel<<<M_PTS / 32, 256>>>(feat, W1, b1);

    mlp_kernel<<<M_PTS / 2, 128>>>(W2, b2, out);
}